// round 11
// baseline (speedup 1.0000x reference)
#include <cuda_runtime.h>
#include <cooperative_groups.h>
namespace cg = cooperative_groups;

// Problem constants (fixed shapes from the reference setup)
#define NB   16      // batch
#define NT   128     // time
#define NHWC 25088   // 56*56*8 floats per frame
#define NS4  6272    // NHWC / 4 (float4 strips per frame)
#define NC   8       // channels
#define BT   224     // block threads; NS4 = 28 * 224 exactly
#define NW   (BT / 32)              // 7 warps
#define NBLK_S (NS4 / BT)           // 28 blocks over the spatial strip
#define NBLKS  (NB * NBLK_S)        // 448 total blocks (all co-resident)
#define NFLD   17                   // 8 act + 8 tot + 1 ttv

// Scratch (no device allocation allowed -> __device__ globals).
// FIELD-MAJOR layout: g_part[field][slot] -> coalesced tail reads.
// Every block writes all its fields every launch => no zeroing needed.
__device__ float g_part[NFLD][NBLKS];

__global__ __launch_bounds__(BT) void fused_coop_kernel(const float4* __restrict__ x,
                                                        const int*   __restrict__ length,
                                                        const float* __restrict__ count,
                                                        float*       __restrict__ out) {
    const int s4  = blockIdx.x * BT + threadIdx.x;   // always < NS4
    const int b   = blockIdx.y;
    const int len = __ldg(&length[b]);
    const float4* base = x + (size_t)b * NT * NS4 + s4;

    float ax = 0.f, ay = 0.f, az = 0.f, aw = 0.f;   // active sums (4 channels)
    float tx = 0.f, ty = 0.f, tz = 0.f, tw = 0.f;   // total sums
    float ttv = 0.f;
    float px = 0.f, py = 0.f, pz = 0.f, pw = 0.f;   // previous masked frame

    #pragma unroll 8
    for (int t = 0; t < NT; ++t) {
        float4 v = __ldcs(&base[(size_t)t * NS4]);
        tx += v.x; ty += v.y; tz += v.z; tw += v.w;
        float cx, cy, cz, cw;
        if (t < len) {
            cx = v.x; cy = v.y; cz = v.z; cw = v.w;
            ax += v.x; ay += v.y; az += v.z; aw += v.w;
        } else {
            cx = 0.f; cy = 0.f; cz = 0.f; cw = 0.f;
        }
        if (t > 0) {
            ttv += fabsf(cx - px) + fabsf(cy - py) + fabsf(cz - pz) + fabsf(cw - pw);
        }
        px = cx; py = cy; pz = cz; pw = cw;
    }

    // --- block reduction ---
    #pragma unroll
    for (int m = 16; m >= 1; m >>= 1)
        ttv += __shfl_xor_sync(0xffffffffu, ttv, m);
    // Parity-preserving reduce: even lanes hold channels 0-3, odd lanes 4-7
    #pragma unroll
    for (int m = 2; m <= 16; m <<= 1) {
        ax += __shfl_xor_sync(0xffffffffu, ax, m);
        ay += __shfl_xor_sync(0xffffffffu, ay, m);
        az += __shfl_xor_sync(0xffffffffu, az, m);
        aw += __shfl_xor_sync(0xffffffffu, aw, m);
        tx += __shfl_xor_sync(0xffffffffu, tx, m);
        ty += __shfl_xor_sync(0xffffffffu, ty, m);
        tz += __shfl_xor_sync(0xffffffffu, tz, m);
        tw += __shfl_xor_sync(0xffffffffu, tw, m);
    }

    __shared__ float sh_a[NW][NC];
    __shared__ float sh_t[NW][NC];
    __shared__ float sh_v[NW];
    const int w = threadIdx.x >> 5, lane = threadIdx.x & 31;
    if (lane == 0) {
        sh_a[w][0] = ax; sh_a[w][1] = ay; sh_a[w][2] = az; sh_a[w][3] = aw;
        sh_t[w][0] = tx; sh_t[w][1] = ty; sh_t[w][2] = tz; sh_t[w][3] = tw;
        sh_v[w] = ttv;
    } else if (lane == 1) {
        sh_a[w][4] = ax; sh_a[w][5] = ay; sh_a[w][6] = az; sh_a[w][7] = aw;
        sh_t[w][4] = tx; sh_t[w][5] = ty; sh_t[w][6] = tz; sh_t[w][7] = tw;
    }
    __syncthreads();

    const int slot = b * NBLK_S + blockIdx.x;
    if (threadIdx.x < NC) {
        const int c = threadIdx.x;
        float sa = 0.f, st = 0.f;
        #pragma unroll
        for (int w2 = 0; w2 < NW; ++w2) { sa += sh_a[w2][c]; st += sh_t[w2][c]; }
        g_part[c][slot]      = sa;
        g_part[NC + c][slot] = st;
    } else if (threadIdx.x == NC) {
        float s = 0.f;
        #pragma unroll
        for (int w2 = 0; w2 < NW; ++w2) s += sh_v[w2];
        g_part[16][slot] = s;
    }

    // --- grid-wide barrier (HW cooperative sync; memory visible after) ---
    cg::this_grid().sync();

    // --- tail: one block per batch (blockIdx.x == 0) ---
    if (blockIdx.x != 0) return;

    __shared__ float sh_fld[NFLD];
    __shared__ float sh_tv[NW];

    // Fields: warp w reduces rows {w, w+7, w+14} over this batch's 28 slots
    // (coalesced; lanes 0-27 valid).
    for (int r = w; r < NFLD; r += NW) {
        float acc = (lane < NBLK_S) ? __ldcg(&g_part[r][b * NBLK_S + lane]) : 0.f;
        #pragma unroll
        for (int m = 16; m >= 1; m >>= 1)
            acc += __shfl_xor_sync(0xffffffffu, acc, m);
        if (lane == 0) sh_fld[r] = acc;
    }

    // Global TTV: every batch-block sums the whole 448-entry ttv row.
    {
        float v = __ldcg(&g_part[16][threadIdx.x]) +
                  __ldcg(&g_part[16][BT + threadIdx.x]);
        #pragma unroll
        for (int m = 16; m >= 1; m >>= 1)
            v += __shfl_xor_sync(0xffffffffu, v, m);
        if (lane == 0) sh_tv[w] = v;
    }
    __syncthreads();

    if (threadIdx.x == 0) {
        float tv = 0.f;
        #pragma unroll
        for (int i = 0; i < NW; ++i) tv += sh_tv[i];
        float ah = 0.f, bh = 0.f;
        #pragma unroll
        for (int c = 0; c < NC; ++c) {
            const float aa = sh_fld[c];
            const float tt = sh_fld[NC + c];
            float e  = aa - __ldg(&count[b * NC + c]);
            float ae = fabsf(e);
            ah += (ae <= 1.f) ? 0.5f * e * e : (ae - 0.5f);
            float eb  = tt - aa;
            float aeb = fabsf(eb);
            bh += (aeb <= 1.f) ? 0.5f * eb * eb : (aeb - 0.5f);
        }
        out[b] = ah * (1.f / NC) + bh * (1.f / NC) + tv * 0.1f;
    }
}

extern "C" void kernel_launch(void* const* d_in, const int* in_sizes, int n_in,
                              void* d_out, int out_size) {
    const float* cam    = (const float*)d_in[0];
    const float* count  = (const float*)d_in[1];
    const int*   length = (const int*)d_in[2];
    float*       out    = (float*)d_out;

    const float4* xv = (const float4*)cam;
    void* args[] = { (void*)&xv, (void*)&length, (void*)&count, (void*)&out };
    dim3 grid(NBLK_S, NB);   // 28 x 16 = 448 blocks, fully co-resident
    dim3 block(BT);
    cudaLaunchCooperativeKernel((const void*)fused_coop_kernel, grid, block, args, 0, (cudaStream_t)0);
}